// round 14
// baseline (speedup 1.0000x reference)
#include <cuda_runtime.h>

#define RES      64
#define R3       (RES * RES * RES)      // 262144
#define NWORDS   (R3 / 32)              // 8192  (32 KB bitmask)
#define NT       352                    // 11 warps/block
#define NBLK     4                      // blocks/SM -> 44 warps/SM, 46-reg cap
#define NB       (148 * NBLK)           // 592
#define NHALF    (NB / 2)               // 296 per transform family

// ---- scratch (no allocations allowed) --------------------------------------
__device__ float4   g_table[R3];        // closest point per voxel (w unused)
__device__ unsigned g_bits[NWORDS];     // voxel occupancy bitmask
__device__ float    g_params[48];       // [t*5+j]: refl ; [16+t*9+j]: rot matrix
__device__ float    g_partials[NB];
__device__ int      g_counter;

// ---- prep: params + table + bitmask + counter reset (vectorized) ------------
__global__ void prep_k(const float4* __restrict__ cp4,
                       const int4*   __restrict__ vox4,
                       const float*  __restrict__ planes,
                       const float*  __restrict__ axes) {
    int j = blockIdx.x * blockDim.x + threadIdx.x;
    if (j == 0) {
        g_counter = 0;
#pragma unroll
        for (int t = 0; t < 3; t++) {
            float nx = planes[4*t+0], ny = planes[4*t+1],
                  nz = planes[4*t+2], d  = planes[4*t+3];
            float s = 2.0f / (nx*nx + ny*ny + nz*nz);
            g_params[t*5+0] = nx;
            g_params[t*5+1] = ny;
            g_params[t*5+2] = nz;
            g_params[t*5+3] = s;
            g_params[t*5+4] = s * d;
        }
#pragma unroll
        for (int t = 0; t < 3; t++) {
            float w = axes[4*t+0], x = axes[4*t+1],
                  y = axes[4*t+2], z = axes[4*t+3];
            // q p q* (pure p, q unnormalized) = [(w^2-|v|^2)I + 2 v v^T + 2 w [v]x] p
            float* m = &g_params[16 + t*9];
            m[0] = w*w + x*x - y*y - z*z;
            m[1] = 2.0f * (x*y - w*z);
            m[2] = 2.0f * (x*z + w*y);
            m[3] = 2.0f * (x*y + w*z);
            m[4] = w*w - x*x + y*y - z*z;
            m[5] = 2.0f * (y*z - w*x);
            m[6] = 2.0f * (x*z - w*y);
            m[7] = 2.0f * (y*z + w*x);
            m[8] = w*w - x*x - y*y + z*z;
        }
    }
    if (j < R3 / 4) {
        float4 a = cp4[3*j + 0];      // x0 y0 z0 x1
        float4 b = cp4[3*j + 1];      // y1 z1 x2 y2
        float4 c = cp4[3*j + 2];      // z2 x3 y3 z3
        g_table[4*j + 0] = make_float4(a.x, a.y, a.z, 0.0f);
        g_table[4*j + 1] = make_float4(a.w, b.x, b.y, 0.0f);
        g_table[4*j + 2] = make_float4(b.z, b.w, c.x, 0.0f);
        g_table[4*j + 3] = make_float4(c.y, c.z, c.w, 0.0f);
    }
    if (j < NWORDS) {
        unsigned w = 0u;
#pragma unroll
        for (int q = 0; q < 8; q++) {
            int4 v = vox4[j*8 + q];
            if (v.x) w |= 1u << (q*4 + 0);
            if (v.y) w |= 1u << (q*4 + 1);
            if (v.z) w |= 1u << (q*4 + 2);
            if (v.w) w |= 1u << (q*4 + 3);
        }
        g_bits[j] = w;
    }
}

// 3 predicated taps for one point. Slimmed issue path:
//  - float-side clamps (FMNMX, fma pipe) instead of integer IMNMX (alu pipe)
//  - index combine via 2 IMAD instead of shifts/ors
//  - live flag folded into the index sign bit in 3 ops:
//      eidx = idx | ((word << ((~idx)&31)) & 0x80000000)
// Dead lanes issue NO load; dests default to the query point -> d2 = 0
// -> sqrt.approx(0) = 0, so no mask math at all.
__device__ __forceinline__ float taps3(const float tx[3], const float ty[3],
                                       const float tz[3],
                                       const unsigned* __restrict__ s_bits) {
    int eidx[3];
#pragma unroll
    for (int t = 0; t < 3; t++) {
        float fx = fminf(fmaxf(tx[t] * 64.0f, 0.0f), 63.0f);
        float fy = fminf(fmaxf(ty[t] * 64.0f, 0.0f), 63.0f);
        float fz = fminf(fmaxf(tz[t] * 64.0f, 0.0f), 63.0f);
        int idx = (__float2int_rd(fx) * 64 + __float2int_rd(fy)) * 64
                  + __float2int_rd(fz);
        unsigned word = s_bits[idx >> 5];
        unsigned sh   = (~(unsigned)idx) & 31u;      // 31 - (idx & 31)
        eidx[t] = idx | (int)((word << sh) & 0x80000000u);  // MSB = live
    }
    float acc = 0.0f;
#pragma unroll
    for (int t = 0; t < 3; t++) {
        float cx = tx[t], cy = ty[t], cz = tz[t], cw = 0.0f;
        const float4* p = &g_table[eidx[t] & 0x3FFFF];
        asm("{\n\t"
            ".reg .pred lp;\n\t"
            "setp.lt.s32 lp, %4, 0;\n\t"
            "@lp ld.global.nc.v4.f32 {%0, %1, %2, %3}, [%5];\n\t"
            "}"
            : "+f"(cx), "+f"(cy), "+f"(cz), "+f"(cw)
            : "r"(eidx[t]), "l"(p));
        float dx = tx[t] - cx, dy = ty[t] - cy, dz = tz[t] - cz;
        float d2 = fmaf(dx, dx, fmaf(dy, dy, dz * dz));
        float dist;
        asm("sqrt.approx.f32 %0, %1;" : "=f"(dist) : "f"(d2));  // sqrt(0)=0
        acc += dist;
    }
    return acc;
}

__device__ __forceinline__ float point_refl(float x, float y, float z,
                                            const float pn[3][5],
                                            const unsigned* __restrict__ s_bits) {
    float tx[3], ty[3], tz[3];
#pragma unroll
    for (int t = 0; t < 3; t++) {
        float dot  = fmaf(x, pn[t][0], fmaf(y, pn[t][1], z * pn[t][2]));
        float coef = fmaf(dot, pn[t][3], pn[t][4]);
        tx[t] = fmaf(-coef, pn[t][0], x);
        ty[t] = fmaf(-coef, pn[t][1], y);
        tz[t] = fmaf(-coef, pn[t][2], z);
    }
    return taps3(tx, ty, tz, s_bits);
}

__device__ __forceinline__ float point_rot(float x, float y, float z,
                                           const float m[3][9],
                                           const unsigned* __restrict__ s_bits) {
    float tx[3], ty[3], tz[3];
#pragma unroll
    for (int t = 0; t < 3; t++) {
        tx[t] = fmaf(x, m[t][0], fmaf(y, m[t][1], z * m[t][2]));
        ty[t] = fmaf(x, m[t][3], fmaf(y, m[t][4], z * m[t][5]));
        tz[t] = fmaf(x, m[t][6], fmaf(y, m[t][7], z * m[t][8]));
    }
    return taps3(tx, ty, tz, s_bits);
}

// ---- main kernel: blocks [0,NHALF) do reflections, [NHALF,NB) rotations ------
__global__ void __launch_bounds__(NT, NBLK)
symmetry_main_k(const float* __restrict__ sp, int npts, float* __restrict__ out) {
    __shared__ unsigned s_bits[NWORDS];   // 32 KB
    __shared__ float    s_red[(NT + 31) / 32];
    __shared__ bool     s_last;

    for (int i = threadIdx.x; i < NWORDS; i += NT)
        s_bits[i] = g_bits[i];
    __syncthreads();

    const bool is_rot = (blockIdx.x >= NHALF);
    const int  bid    = is_rot ? (blockIdx.x - NHALF) : blockIdx.x;

    const float4* sp4 = (const float4*)sp;
    const int ngroups = npts >> 2;     // 4 points = 3 float4
    const int stride  = NHALF * NT;
    const int tail    = npts & 3;
    float acc = 0.0f;

    if (!is_rot) {
        float pn[3][5];
#pragma unroll
        for (int t = 0; t < 3; t++)
#pragma unroll
            for (int j = 0; j < 5; j++) pn[t][j] = g_params[t*5 + j];

        for (int g = bid * NT + threadIdx.x; g < ngroups; g += stride) {
            float4 A = __ldg(&sp4[3*g + 0]);
            float4 B = __ldg(&sp4[3*g + 1]);
            float4 C = __ldg(&sp4[3*g + 2]);
            float X[4] = {A.x, A.w, B.z, C.y};
            float Y[4] = {A.y, B.x, B.w, C.z};
            float Z[4] = {A.z, B.y, C.x, C.w};
#pragma unroll
            for (int k = 0; k < 4; k++)
                acc += point_refl(X[k], Y[k], Z[k], pn, s_bits);
        }
        if (tail && bid == 0 && threadIdx.x < tail) {
            int i = npts - tail + threadIdx.x;
            acc += point_refl(sp[3*i], sp[3*i+1], sp[3*i+2], pn, s_bits);
        }
    } else {
        float m[3][9];
#pragma unroll
        for (int t = 0; t < 3; t++)
#pragma unroll
            for (int j = 0; j < 9; j++) m[t][j] = g_params[16 + t*9 + j];

        for (int g = bid * NT + threadIdx.x; g < ngroups; g += stride) {
            float4 A = __ldg(&sp4[3*g + 0]);
            float4 B = __ldg(&sp4[3*g + 1]);
            float4 C = __ldg(&sp4[3*g + 2]);
            float X[4] = {A.x, A.w, B.z, C.y};
            float Y[4] = {A.y, B.x, B.w, C.z};
            float Z[4] = {A.z, B.y, C.x, C.w};
#pragma unroll
            for (int k = 0; k < 4; k++)
                acc += point_rot(X[k], Y[k], Z[k], m, s_bits);
        }
        if (tail && bid == 0 && threadIdx.x < tail) {
            int i = npts - tail + threadIdx.x;
            acc += point_rot(sp[3*i], sp[3*i+1], sp[3*i+2], m, s_bits);
        }
    }

    // deterministic block reduction (NT/32 = 11 warps)
#pragma unroll
    for (int o = 16; o; o >>= 1)
        acc += __shfl_xor_sync(0xFFFFFFFFu, acc, o);
    int lane = threadIdx.x & 31;
    int wid  = threadIdx.x >> 5;
    if (lane == 0) s_red[wid] = acc;
    __syncthreads();
    if (threadIdx.x == 0) {
        float v = 0.0f;
#pragma unroll
        for (int w = 0; w < NT / 32; w++) v += s_red[w];
        g_partials[blockIdx.x] = v;
        __threadfence();
        unsigned old = atomicAdd(&g_counter, 1);
        s_last = (old == (unsigned)(gridDim.x - 1));
    }
    __syncthreads();

    // last-arriving block performs the final deterministic reduction
    if (s_last) {
        __threadfence();
        float v = 0.0f;
        for (int i = threadIdx.x; i < NB; i += NT)
            v += g_partials[i];
#pragma unroll
        for (int o = 16; o; o >>= 1)
            v += __shfl_xor_sync(0xFFFFFFFFu, v, o);
        if (lane == 0) s_red[wid] = v;
        __syncthreads();
        if (threadIdx.x == 0) {
            float u = 0.0f;
#pragma unroll
            for (int w = 0; w < NT / 32; w++) u += s_red[w];
            out[0] = u / (float)npts;
        }
    }
}

// ---- launch ------------------------------------------------------------------
extern "C" void kernel_launch(void* const* d_in, const int* in_sizes, int n_in,
                              void* d_out, int out_size) {
    const float* sp     = (const float*)d_in[0];   // sample_points (N,3)
    const float* cp     = (const float*)d_in[1];   // closest_points (R^3,3)
    const int*   vox    = (const int*)  d_in[2];   // voxels (R^3,)
    const float* planes = (const float*)d_in[3];   // (3,4)
    const float* axes   = (const float*)d_in[4];   // (3,4)
    int npts = in_sizes[0] / 3;

    prep_k<<<R3 / 4 / 256, 256>>>((const float4*)cp, (const int4*)vox,
                                  planes, axes);
    symmetry_main_k<<<NB, NT>>>(sp, npts, (float*)d_out);
}

// round 15
// speedup vs baseline: 1.0061x; 1.0061x over previous
#include <cuda_runtime.h>

#define RES      64
#define R3       (RES * RES * RES)      // 262144
#define NWORDS   (R3 / 32)              // 8192  (32 KB bitmask)
#define NT       352                    // 11 warps/block
#define NBLK     4                      // blocks/SM -> 44 warps/SM, 46-reg cap
#define NB       (148 * NBLK)           // 592
#define NHALF    (NB / 2)               // 296 per transform family

// ---- scratch (no allocations allowed) --------------------------------------
__device__ float4   g_table[R3];        // closest point per voxel (w unused)
__device__ unsigned g_bits[NWORDS];     // voxel occupancy bitmask
__device__ float    g_params[48];       // [t*5+j]: refl ; [16+t*9+j]: rot matrix
__device__ float    g_partials[NB];
__device__ int      g_counter;

// ---- prep: params + table + bitmask + counter reset (vectorized) ------------
__global__ void prep_k(const float4* __restrict__ cp4,
                       const int4*   __restrict__ vox4,
                       const float*  __restrict__ planes,
                       const float*  __restrict__ axes) {
    int j = blockIdx.x * blockDim.x + threadIdx.x;
    if (j == 0) {
        g_counter = 0;
#pragma unroll
        for (int t = 0; t < 3; t++) {
            float nx = planes[4*t+0], ny = planes[4*t+1],
                  nz = planes[4*t+2], d  = planes[4*t+3];
            float s = 2.0f / (nx*nx + ny*ny + nz*nz);
            g_params[t*5+0] = nx;
            g_params[t*5+1] = ny;
            g_params[t*5+2] = nz;
            g_params[t*5+3] = s;
            g_params[t*5+4] = s * d;
        }
#pragma unroll
        for (int t = 0; t < 3; t++) {
            float w = axes[4*t+0], x = axes[4*t+1],
                  y = axes[4*t+2], z = axes[4*t+3];
            // q p q* (pure p, q unnormalized) = [(w^2-|v|^2)I + 2 v v^T + 2 w [v]x] p
            float* m = &g_params[16 + t*9];
            m[0] = w*w + x*x - y*y - z*z;
            m[1] = 2.0f * (x*y - w*z);
            m[2] = 2.0f * (x*z + w*y);
            m[3] = 2.0f * (x*y + w*z);
            m[4] = w*w - x*x + y*y - z*z;
            m[5] = 2.0f * (y*z - w*x);
            m[6] = 2.0f * (x*z - w*y);
            m[7] = 2.0f * (y*z + w*x);
            m[8] = w*w - x*x - y*y + z*z;
        }
    }
    if (j < R3 / 4) {
        float4 a = cp4[3*j + 0];      // x0 y0 z0 x1
        float4 b = cp4[3*j + 1];      // y1 z1 x2 y2
        float4 c = cp4[3*j + 2];      // z2 x3 y3 z3
        g_table[4*j + 0] = make_float4(a.x, a.y, a.z, 0.0f);
        g_table[4*j + 1] = make_float4(a.w, b.x, b.y, 0.0f);
        g_table[4*j + 2] = make_float4(b.z, b.w, c.x, 0.0f);
        g_table[4*j + 3] = make_float4(c.y, c.z, c.w, 0.0f);
    }
    if (j < NWORDS) {
        unsigned w = 0u;
#pragma unroll
        for (int q = 0; q < 8; q++) {
            int4 v = vox4[j*8 + q];
            if (v.x) w |= 1u << (q*4 + 0);
            if (v.y) w |= 1u << (q*4 + 1);
            if (v.z) w |= 1u << (q*4 + 2);
            if (v.w) w |= 1u << (q*4 + 3);
        }
        g_bits[j] = w;
    }
}

// streaming point load: evict-first so the 48MB stream doesn't thrash the
// L1 lines holding gather-table data
__device__ __forceinline__ float4 ldg_stream(const float4* p) {
    float4 v;
    asm("ld.global.nc.L1::evict_first.v4.f32 {%0, %1, %2, %3}, [%4];"
        : "=f"(v.x), "=f"(v.y), "=f"(v.z), "=f"(v.w) : "l"(p));
    return v;
}

// ---- voxel index from transformed coords ------------------------------------
__device__ __forceinline__ int vidx(float x, float y, float z) {
    int ix = min(max(__float2int_rd(x * 64.0f), 0), 63);
    int iy = min(max(__float2int_rd(y * 64.0f), 0), 63);
    int iz = min(max(__float2int_rd(z * 64.0f), 0), 63);
    return (ix << 12) | (iy << 6) | iz;
}

// 3 predicated taps for one point. Live bit rides in the index MSB.
// Dead lanes issue NO load; dests default to the query point -> d2 = 0
// -> sqrt.approx(0) = 0, so no mask math at all.
__device__ __forceinline__ float taps3(const float tx[3], const float ty[3],
                                       const float tz[3],
                                       const unsigned* __restrict__ s_bits) {
    int eidx[3];
#pragma unroll
    for (int t = 0; t < 3; t++) {
        int idx = vidx(tx[t], ty[t], tz[t]);
        unsigned live = (s_bits[idx >> 5] >> (idx & 31)) & 1u;
        eidx[t] = idx | (int)(live << 31);          // MSB set = live
    }
    float acc = 0.0f;
#pragma unroll
    for (int t = 0; t < 3; t++) {
        float cx = tx[t], cy = ty[t], cz = tz[t], cw = 0.0f;
        const float4* p = &g_table[eidx[t] & 0x3FFFF];
        asm("{\n\t"
            ".reg .pred lp;\n\t"
            "setp.lt.s32 lp, %4, 0;\n\t"
            "@lp ld.global.nc.v4.f32 {%0, %1, %2, %3}, [%5];\n\t"
            "}"
            : "+f"(cx), "+f"(cy), "+f"(cz), "+f"(cw)
            : "r"(eidx[t]), "l"(p));
        float dx = tx[t] - cx, dy = ty[t] - cy, dz = tz[t] - cz;
        float d2 = fmaf(dx, dx, fmaf(dy, dy, dz * dz));
        float dist;
        asm("sqrt.approx.f32 %0, %1;" : "=f"(dist) : "f"(d2));  // sqrt(0)=0
        acc += dist;
    }
    return acc;
}

__device__ __forceinline__ float point_refl(float x, float y, float z,
                                            const float pn[3][5],
                                            const unsigned* __restrict__ s_bits) {
    float tx[3], ty[3], tz[3];
#pragma unroll
    for (int t = 0; t < 3; t++) {
        float dot  = fmaf(x, pn[t][0], fmaf(y, pn[t][1], z * pn[t][2]));
        float coef = fmaf(dot, pn[t][3], pn[t][4]);
        tx[t] = fmaf(-coef, pn[t][0], x);
        ty[t] = fmaf(-coef, pn[t][1], y);
        tz[t] = fmaf(-coef, pn[t][2], z);
    }
    return taps3(tx, ty, tz, s_bits);
}

__device__ __forceinline__ float point_rot(float x, float y, float z,
                                           const float m[3][9],
                                           const unsigned* __restrict__ s_bits) {
    float tx[3], ty[3], tz[3];
#pragma unroll
    for (int t = 0; t < 3; t++) {
        tx[t] = fmaf(x, m[t][0], fmaf(y, m[t][1], z * m[t][2]));
        ty[t] = fmaf(x, m[t][3], fmaf(y, m[t][4], z * m[t][5]));
        tz[t] = fmaf(x, m[t][6], fmaf(y, m[t][7], z * m[t][8]));
    }
    return taps3(tx, ty, tz, s_bits);
}

// ---- main kernel: blocks [0,NHALF) do reflections, [NHALF,NB) rotations ------
__global__ void __launch_bounds__(NT, NBLK)
symmetry_main_k(const float* __restrict__ sp, int npts, float* __restrict__ out) {
    __shared__ unsigned s_bits[NWORDS];   // 32 KB
    __shared__ float    s_red[(NT + 31) / 32];
    __shared__ bool     s_last;

    for (int i = threadIdx.x; i < NWORDS; i += NT)
        s_bits[i] = g_bits[i];
    __syncthreads();

    const bool is_rot = (blockIdx.x >= NHALF);
    const int  bid    = is_rot ? (blockIdx.x - NHALF) : blockIdx.x;

    const float4* sp4 = (const float4*)sp;
    const int ngroups = npts >> 2;     // 4 points = 3 float4
    const int stride  = NHALF * NT;
    const int tail    = npts & 3;
    float acc = 0.0f;

    if (!is_rot) {
        float pn[3][5];
#pragma unroll
        for (int t = 0; t < 3; t++)
#pragma unroll
            for (int j = 0; j < 5; j++) pn[t][j] = g_params[t*5 + j];

        for (int g = bid * NT + threadIdx.x; g < ngroups; g += stride) {
            float4 A = ldg_stream(&sp4[3*g + 0]);
            float4 B = ldg_stream(&sp4[3*g + 1]);
            float4 C = ldg_stream(&sp4[3*g + 2]);
            float X[4] = {A.x, A.w, B.z, C.y};
            float Y[4] = {A.y, B.x, B.w, C.z};
            float Z[4] = {A.z, B.y, C.x, C.w};
#pragma unroll
            for (int k = 0; k < 4; k++)
                acc += point_refl(X[k], Y[k], Z[k], pn, s_bits);
        }
        if (tail && bid == 0 && threadIdx.x < tail) {
            int i = npts - tail + threadIdx.x;
            acc += point_refl(sp[3*i], sp[3*i+1], sp[3*i+2], pn, s_bits);
        }
    } else {
        float m[3][9];
#pragma unroll
        for (int t = 0; t < 3; t++)
#pragma unroll
            for (int j = 0; j < 9; j++) m[t][j] = g_params[16 + t*9 + j];

        for (int g = bid * NT + threadIdx.x; g < ngroups; g += stride) {
            float4 A = ldg_stream(&sp4[3*g + 0]);
            float4 B = ldg_stream(&sp4[3*g + 1]);
            float4 C = ldg_stream(&sp4[3*g + 2]);
            float X[4] = {A.x, A.w, B.z, C.y};
            float Y[4] = {A.y, B.x, B.w, C.z};
            float Z[4] = {A.z, B.y, C.x, C.w};
#pragma unroll
            for (int k = 0; k < 4; k++)
                acc += point_rot(X[k], Y[k], Z[k], m, s_bits);
        }
        if (tail && bid == 0 && threadIdx.x < tail) {
            int i = npts - tail + threadIdx.x;
            acc += point_rot(sp[3*i], sp[3*i+1], sp[3*i+2], m, s_bits);
        }
    }

    // deterministic block reduction (NT/32 = 11 warps)
#pragma unroll
    for (int o = 16; o; o >>= 1)
        acc += __shfl_xor_sync(0xFFFFFFFFu, acc, o);
    int lane = threadIdx.x & 31;
    int wid  = threadIdx.x >> 5;
    if (lane == 0) s_red[wid] = acc;
    __syncthreads();
    if (threadIdx.x == 0) {
        float v = 0.0f;
#pragma unroll
        for (int w = 0; w < NT / 32; w++) v += s_red[w];
        g_partials[blockIdx.x] = v;
        __threadfence();
        unsigned old = atomicAdd(&g_counter, 1);
        s_last = (old == (unsigned)(gridDim.x - 1));
    }
    __syncthreads();

    // last-arriving block performs the final deterministic reduction
    if (s_last) {
        __threadfence();
        float v = 0.0f;
        for (int i = threadIdx.x; i < NB; i += NT)
            v += g_partials[i];
#pragma unroll
        for (int o = 16; o; o >>= 1)
            v += __shfl_xor_sync(0xFFFFFFFFu, v, o);
        if (lane == 0) s_red[wid] = v;
        __syncthreads();
        if (threadIdx.x == 0) {
            float u = 0.0f;
#pragma unroll
            for (int w = 0; w < NT / 32; w++) u += s_red[w];
            out[0] = u / (float)npts;
        }
    }
}

// ---- launch ------------------------------------------------------------------
extern "C" void kernel_launch(void* const* d_in, const int* in_sizes, int n_in,
                              void* d_out, int out_size) {
    const float* sp     = (const float*)d_in[0];   // sample_points (N,3)
    const float* cp     = (const float*)d_in[1];   // closest_points (R^3,3)
    const int*   vox    = (const int*)  d_in[2];   // voxels (R^3,)
    const float* planes = (const float*)d_in[3];   // (3,4)
    const float* axes   = (const float*)d_in[4];   // (3,4)
    int npts = in_sizes[0] / 3;

    prep_k<<<R3 / 4 / 256, 256>>>((const float4*)cp, (const int4*)vox,
                                  planes, axes);
    symmetry_main_k<<<NB, NT>>>(sp, npts, (float*)d_out);
}